// round 8
// baseline (speedup 1.0000x reference)
#include <cuda_runtime.h>
#include <stdint.h>

#define NB 2
#define NH 4
#define NN 8192
#define NK 32
#define NROWS 8
#define PERM_ELEMS (NB * NN * NH * NK * NK)   // 67,108,864
#define IDX_BASE   PERM_ELEMS

typedef unsigned long long u64;
typedef unsigned int u32;

// Scratch (device globals -> no allocation)
__device__ u64 g_keys[NROWS * NN];
__device__ int g_inv [NROWS * NN];

__device__ __forceinline__ u32 f2u(float f) {
    u32 b = __float_as_uint(f);
    return (b & 0x80000000u) ? ~b : (b | 0x80000000u);
}
__device__ __forceinline__ void cswap(u64& a, u64& b, bool asc) {
    if ((a > b) == asc) { u64 t = a; a = b; b = t; }
}
__device__ __forceinline__ void cluster_sync() {
    asm volatile("barrier.cluster.arrive.aligned;" ::: "memory");
    asm volatile("barrier.cluster.wait.aligned;" ::: "memory");
}
__device__ __forceinline__ u32 smem_u32(const void* p) {
    u32 a;
    asm("{ .reg .u64 t; cvta.to.shared.u64 t, %1; cvt.u32.u64 %0, t; }"
        : "=r"(a) : "l"(p));
    return a;
}
__device__ __forceinline__ u32 mapa_rank(u32 local, u32 rank) {
    u32 r;
    asm("mapa.shared::cluster.u32 %0, %1, %2;" : "=r"(r) : "r"(local), "r"(rank));
    return r;
}

// One shfl_xor compare-exchange step on the 4-consecutive-element register
// layout (element global idx = base + tid*4 + e). Valid for j in {4..64}:
// partner of idx is same slot e on lane^(j>>2). asc uniform per thread (k>=8).
__device__ __forceinline__ void shfl_step(u64 e[4], int lane, int d, bool asc) {
#pragma unroll
    for (int m = 0; m < 4; m++) {
        u64 o = __shfl_xor_sync(0xFFFFFFFFu, e[m], d);
        bool low = ((lane & d) == 0);
        bool take = (asc == low) ? (o < e[m]) : (o > e[m]);
        if (take) e[m] = o;
    }
}
// In-thread j=2,1 finish.
__device__ __forceinline__ void reg_tail(u64 e[4], bool asc) {
    cswap(e[0], e[2], asc); cswap(e[1], e[3], asc);   // j=2
    cswap(e[0], e[1], asc); cswap(e[2], e[3], asc);   // j=1
}
// j = 64..4 via shfl, then j=2,1 in regs.
__device__ __forceinline__ void shfl_finish(u64 e[4], int lane, bool asc) {
    shfl_step(e, lane, 16, asc);   // j=64
    shfl_step(e, lane,  8, asc);   // j=32
    shfl_step(e, lane,  4, asc);   // j=16
    shfl_step(e, lane,  2, asc);   // j=8
    shfl_step(e, lane,  1, asc);   // j=4
    reg_tail(e, asc);
}

// Block-wide step over the 2048-elem chunk (j >= 128).
__device__ __forceinline__ void block_step(u64* sh, int gbase, int tid,
                                           int j, int k) {
#pragma unroll
    for (int t = tid; t < 1024; t += 512) {
        int i = ((t & ~(j - 1)) << 1) | (t & (j - 1));
        int p = i | j;
        bool asc = (((gbase + i) & k) == 0);
        u64 a = sh[i], b = sh[p];
        if ((a > b) == asc) { sh[i] = b; sh[p] = a; }
    }
    __syncthreads();
}

// Double-buffered cross-CTA exchange: ONE cluster_sync, read peer src,
// write own dst. Keys unique -> both sides decide consistently.
__device__ __forceinline__ void exchange(const u64* src, u64* dst,
                                         u32 src_sm, int partner,
                                         bool keep_min, int tid) {
    cluster_sync();                         // peers' src finalized
    u64 peer[4];
    u32 remote = mapa_rank(src_sm, (u32)partner);
#pragma unroll
    for (int m = 0; m < 4; m++) {
        u32 addr = remote + (u32)((tid + (m << 9)) << 3);
        asm volatile("ld.shared::cluster.b64 %0, [%1];" : "=l"(peer[m]) : "r"(addr));
    }
#pragma unroll
    for (int m = 0; m < 4; m++) {
        int l = tid + (m << 9);
        u64 mine = src[l];
        bool pick = keep_min ? (peer[m] < mine) : (peer[m] > mine);
        dst[l] = pick ? peer[m] : mine;
    }
}

// -------------------------------------------------------------------------
// Full stable argsort of 8 rows x 8192, ONE launch.
// 8 clusters x 4 CTAs, 2048-elem chunk per CTA.
//   k=2..128   : entirely in registers (4 consec elems/thread, shfl_xor)
//   k=256..2048: smem block steps j>=128, reg/shfl finish j<=64
//   k=4096/8192: double-buffered DSMEM exchanges + local steps
// Extracts sorted keys + inverse permutation straight from registers.
// -------------------------------------------------------------------------
__global__ void __launch_bounds__(512) __cluster_dims__(4, 1, 1)
sortCluster(const float* __restrict__ r) {
    __shared__ u64 bufA[2048];
    __shared__ u64 bufB[2048];
    int tid  = threadIdx.x, lane = tid & 31;
    int row  = blockIdx.x >> 2;
    int rank = blockIdx.x & 3;
    int base = rank << 11;
    const float* rr = r + row * NN;
    u32 smA = smem_u32(bufA), smB = smem_u32(bufB);
    int q = tid << 2;                        // chunk-local quad base

    // load 4 consecutive values, build stable ascending keys in regs
    u64 e[4];
    {
        float4 f = *reinterpret_cast<const float4*>(rr + base + q);
        e[0] = ((u64)f2u(f.x) << 32) | (u32)(base + q);
        e[1] = ((u64)f2u(f.y) << 32) | (u32)(base + q + 1);
        e[2] = ((u64)f2u(f.z) << 32) | (u32)(base + q + 2);
        e[3] = ((u64)f2u(f.w) << 32) | (u32)(base + q + 3);
    }

    // ---- k=2,4 in-thread ----
    cswap(e[0], e[1], true); cswap(e[2], e[3], false);        // k=2
    {
        bool a4 = ((q & 4) == 0);                             // k=4
        cswap(e[0], e[2], a4); cswap(e[1], e[3], a4);
        cswap(e[0], e[1], a4); cswap(e[2], e[3], a4);
    }
    // ---- k=8..128 fully in registers ----
    {
        bool a;
        a = ((q & 8) == 0);                                   // k=8
        shfl_step(e, lane, 1, a); reg_tail(e, a);
        a = ((q & 16) == 0);                                  // k=16
        shfl_step(e, lane, 2, a); shfl_step(e, lane, 1, a); reg_tail(e, a);
        a = ((q & 32) == 0);                                  // k=32
        shfl_step(e, lane, 4, a); shfl_step(e, lane, 2, a);
        shfl_step(e, lane, 1, a); reg_tail(e, a);
        a = ((q & 64) == 0);                                  // k=64
        shfl_step(e, lane, 8, a); shfl_step(e, lane, 4, a);
        shfl_step(e, lane, 2, a); shfl_step(e, lane, 1, a); reg_tail(e, a);
        a = ((q & 128) == 0);                                 // k=128
        shfl_finish(e, lane, a);
    }

    // ---- k=256..2048: block steps j>=128 + reg/shfl finish ----
    for (int k = 256; k <= 2048; k <<= 1) {
#pragma unroll
        for (int m = 0; m < 4; m++) bufA[q + m] = e[m];
        __syncthreads();
        for (int j = k >> 1; j >= 128; j >>= 1)
            block_step(bufA, base, tid, j, k);
#pragma unroll
        for (int m = 0; m < 4; m++) e[m] = bufA[q + m];
        bool a = (((base + q) & k) == 0);
        shfl_finish(e, lane, a);
        if (k == 2048) {                      // stage into bufA for exchange
#pragma unroll
            for (int m = 0; m < 4; m++) bufA[q + m] = e[m];
        }
    }

    // ---- k=4096: DSMEM j=2048 (A->B), local j<=1024 ----
    exchange(bufA, bufB, smA, rank ^ 1, ((rank ^ (rank >> 1)) & 1) == 0, tid);
    __syncthreads();
    for (int j = 1024; j >= 128; j >>= 1)
        block_step(bufB, base, tid, j, 4096);
    {
#pragma unroll
        for (int m = 0; m < 4; m++) e[m] = bufB[q + m];
        bool a = (((base + q) & 4096) == 0);
        shfl_finish(e, lane, a);
#pragma unroll
        for (int m = 0; m < 4; m++) bufB[q + m] = e[m];
    }

    // ---- k=8192 (asc): DSMEM j=4096 (B->A), j=2048 (A->B), local ----
    exchange(bufB, bufA, smB, rank ^ 2, rank < 2, tid);
    exchange(bufA, bufB, smA, rank ^ 1, (rank & 1) == 0, tid);
    __syncthreads();
    for (int j = 1024; j >= 128; j >>= 1)
        block_step(bufB, base, tid, j, 8192);
#pragma unroll
    for (int m = 0; m < 4; m++) e[m] = bufB[q + m];
    shfl_finish(e, lane, true);

    // ---- extract straight from registers ----
    u64* gk  = g_keys + row * NN + base;
    int* inv = g_inv  + row * NN;
#pragma unroll
    for (int m = 0; m < 4; m++) {
        gk[q + m] = e[m];
        inv[(u32)e[m] & 8191u] = base + q + m;
    }
}

// -------------------------------------------------------------------------
// Windows + perm generation (validated R7): one warp per window.
// -------------------------------------------------------------------------
__global__ void __launch_bounds__(256) windowsW(float* __restrict__ out) {
    const unsigned FULL = 0xFFFFFFFFu;
    const float E_M8  = 3.3546262790251185e-4f;   // exp(-8)
    const float E_P56 = 2.0916595960130657e+24f;  // exp(56)
    int w    = blockIdx.x * 8 + (threadIdx.x >> 5);
    int lane = threadIdx.x & 31;
    int row  = w >> 13;
    int p    = w & (NN - 1);
    int rb   = row * NN;

    int s   = g_inv[rb + p];
    int pos = (s + lane) & (NN - 1);
    u64 key = g_keys[rb + pos];
    int idx = (int)((u32)key & 8191u);
    u32 u   = (u32)(key >> 32);

    u32 prevu = __shfl_up_sync(FULL, u, 1);
    int eq = (lane > 0 && pos != 0 && u == prevu) ? 1 : 0;
    unsigned mask = __ballot_sync(FULL, eq);

    int t = lane;
    unsigned above = (t == 31) ? 0u : (mask >> (t + 1));
    int t1 = t + (__ffs(~above) - 1);                // tie-run end
    unsigned below = ~mask & (0xFFFFFFFFu >> (31 - t));
    int t0 = 31 - __clz(below);                      // tie-run start
    int m  = NN - s; if (m > 32) m = 32;             // wrap point
    int greater = (t < m) ? (m - 1 - t1) : (m + 31 - t1);
    int rank = greater + (t - t0);

    int pack = (idx << 6) | rank;                    // idx distinct -> stable
#pragma unroll
    for (int k2 = 2; k2 <= 32; k2 <<= 1) {
#pragma unroll
        for (int j = k2 >> 1; j > 0; j >>= 1) {
            int o = __shfl_xor_sync(FULL, pack, j);
            bool asc = ((lane & k2) == 0);
            bool low = ((lane & j) == 0);
            bool take = (asc == low) ? (o < pack) : (o > pack);
            if (take) pack = o;
        }
    }

    __stcs(out + (size_t)IDX_BASE + (size_t)(rb + p) * NK + lane,
           (float)(pack >> 6));
    int rk = pack & 63;

    float e = __expf(-2.0f * (float)lane);           // lane m holds exp(-2m)
    int c0 = (lane & 7) * 4;
    int arow = lane >> 3;

    int mm[4]; float v[4];
    {
        int r0 = __shfl_sync(FULL, rk, c0);
        int r1 = __shfl_sync(FULL, rk, c0 + 1);
        int r2 = __shfl_sync(FULL, rk, c0 + 2);
        int r3 = __shfl_sync(FULL, rk, c0 + 3);
        mm[0] = (arow - r0) & 31;  mm[1] = (arow - r1) & 31;
        mm[2] = (arow - r2) & 31;  mm[3] = (arow - r3) & 31;
        v[0] = __shfl_sync(FULL, e, mm[0]);
        v[1] = __shfl_sync(FULL, e, mm[1]);
        v[2] = __shfl_sync(FULL, e, mm[2]);
        v[3] = __shfl_sync(FULL, e, mm[3]);
    }

    int b = row >> 2, h = row & 3;
    float* po = out + ((size_t)((b * NN + p) * NH + h) << 10);  // (B,N,H,K,K)

    __stcs(reinterpret_cast<float4*>(po + arow * 32 + c0),
           make_float4(v[0], v[1], v[2], v[3]));
#pragma unroll
    for (int rnd = 1; rnd < 8; rnd++) {
#pragma unroll
        for (int c = 0; c < 4; c++) {
            mm[c] += 4;
            bool wrap = mm[c] >= 32;
            v[c] *= wrap ? E_P56 : E_M8;
            if (wrap) mm[c] -= 32;
        }
        int a = rnd * 4 + arow;
        __stcs(reinterpret_cast<float4*>(po + a * 32 + c0),
               make_float4(v[0], v[1], v[2], v[3]));
    }
}

extern "C" void kernel_launch(void* const* d_in, const int* in_sizes, int n_in,
                              void* d_out, int out_size) {
    const float* ranking = (const float*)d_in[0];   // (B,H,N,1) f32
    float* out = (float*)d_out;

    sortCluster<<<32, 512>>>(ranking);
    windowsW<<<8192, 256>>>(out);
}

// round 9
// speedup vs baseline: 1.1868x; 1.1868x over previous
#include <cuda_runtime.h>
#include <stdint.h>

#define NB 2
#define NH 4
#define NN 8192
#define NK 32
#define NROWS 8
#define PERM_ELEMS (NB * NN * NH * NK * NK)   // 67,108,864
#define IDX_BASE   PERM_ELEMS

typedef unsigned long long u64;
typedef unsigned int u32;

// Scratch (device globals -> no allocation)
__device__ u64 g_keys[NROWS * NN];
__device__ int g_inv [NROWS * NN];

__device__ __forceinline__ u32 f2u(float f) {
    u32 b = __float_as_uint(f);
    return (b & 0x80000000u) ? ~b : (b | 0x80000000u);
}
__device__ __forceinline__ void cswap(u64& a, u64& b, bool asc) {
    if ((a > b) == asc) { u64 t = a; a = b; b = t; }
}
__device__ __forceinline__ void cluster_sync() {
    asm volatile("barrier.cluster.arrive.aligned;" ::: "memory");
    asm volatile("barrier.cluster.wait.aligned;" ::: "memory");
}
__device__ __forceinline__ u32 smem_u32(const void* p) {
    u32 a;
    asm("{ .reg .u64 t; cvta.to.shared.u64 t, %1; cvt.u32.u64 %0, t; }"
        : "=r"(a) : "l"(p));
    return a;
}
__device__ __forceinline__ u32 mapa_rank(u32 local, u32 rank) {
    u32 r;
    asm("mapa.shared::cluster.u32 %0, %1, %2;" : "=r"(r) : "r"(local), "r"(rank));
    return r;
}

// Warp-private segment: smem steps j=jhi..4, then j=2,1 in registers
// (thread owns 4 consecutive elems, 32B-aligned -> LDS.128/STS.128).
__device__ __forceinline__ void warp_finish(u64* sh, int seg, int gseg,
                                            int lane, int jhi, int k) {
    for (int j = jhi; j >= 4; j >>= 1) {
#pragma unroll
        for (int t = lane; t < 64; t += 32) {
            int i = ((t & ~(j - 1)) << 1) | (t & (j - 1));
            int p = i | j;
            bool asc = (((gseg + i) & k) == 0);
            u64 a = sh[seg + i], b = sh[seg + p];
            if ((a > b) == asc) { sh[seg + i] = b; sh[seg + p] = a; }
        }
        __syncwarp();
    }
    int eb = seg + (lane << 2);
    bool asc = (((gseg + (lane << 2)) & k) == 0);
    u64 e0 = sh[eb], e1 = sh[eb + 1], e2 = sh[eb + 2], e3 = sh[eb + 3];
    cswap(e0, e2, asc); cswap(e1, e3, asc);    // j=2
    cswap(e0, e1, asc); cswap(e2, e3, asc);    // j=1
    sh[eb] = e0; sh[eb + 1] = e1; sh[eb + 2] = e2; sh[eb + 3] = e3;
    __syncwarp();
}

// Block-wide step over the 2048-elem chunk (j >= 128).
__device__ __forceinline__ void block_step(u64* sh, int gbase, int tid,
                                           int j, int k) {
#pragma unroll
    for (int t = tid; t < 1024; t += 512) {
        int i = ((t & ~(j - 1)) << 1) | (t & (j - 1));
        int p = i | j;
        bool asc = (((gbase + i) & k) == 0);
        u64 a = sh[i], b = sh[p];
        if ((a > b) == asc) { sh[i] = b; sh[p] = a; }
    }
    __syncthreads();
}

// Cross-CTA exchange via DSMEM (keys unique -> both sides decide consistently).
__device__ __forceinline__ void exchange(u64* sh, u32 shbase, int partner,
                                         bool keep_min, int tid) {
    cluster_sync();
    u64 peer[4];
    u32 remote = mapa_rank(shbase, (u32)partner);
#pragma unroll
    for (int m = 0; m < 4; m++) {
        u32 addr = remote + (u32)((tid + (m << 9)) << 3);
        asm volatile("ld.shared::cluster.b64 %0, [%1];" : "=l"(peer[m]) : "r"(addr));
    }
    cluster_sync();
#pragma unroll
    for (int m = 0; m < 4; m++) {
        int l = tid + (m << 9);
        u64 mine = sh[l];
        bool take = keep_min ? (peer[m] < mine) : (peer[m] > mine);
        if (take) sh[l] = peer[m];
    }
}

// -------------------------------------------------------------------------
// Full stable argsort of 8 rows x 8192, ONE launch. (R6-validated)
// 8 clusters x 4 CTAs, 2048-elem chunk per CTA, end-to-end in smem.
// -------------------------------------------------------------------------
__global__ void __launch_bounds__(512) __cluster_dims__(4, 1, 1)
sortCluster(const float* __restrict__ r) {
    __shared__ u64 sh[2048];
    int tid  = threadIdx.x, lane = tid & 31, warp = tid >> 5;
    int row  = blockIdx.x >> 2;
    int rank = blockIdx.x & 3;
    int base = rank << 11;
    const float* rr = r + row * NN;
    u32 shbase = smem_u32(sh);

    for (int l = tid; l < 2048; l += 512) {
        int gi = base + l;
        sh[l] = ((u64)f2u(rr[gi]) << 32) | (u32)gi;   // stable asc key
    }
    __syncthreads();

    int seg  = warp << 7;                   // warp-private 128-elem segment
    int gseg = base + seg;

    // k=2 and k=4 entirely in registers (thread owns 4 consecutive elems)
    {
        int eb = seg + (lane << 2);
        u64 e0 = sh[eb], e1 = sh[eb + 1], e2 = sh[eb + 2], e3 = sh[eb + 3];
        cswap(e0, e1, true); cswap(e2, e3, false);            // k=2
        bool a4 = ((lane & 1) == 0);                          // k=4
        cswap(e0, e2, a4); cswap(e1, e3, a4);
        cswap(e0, e1, a4); cswap(e2, e3, a4);
        sh[eb] = e0; sh[eb + 1] = e1; sh[eb + 2] = e2; sh[eb + 3] = e3;
        __syncwarp();
    }

    // k = 8..128: warp-local (smem j>=4, regs j<=2)
    for (int k = 8; k <= 128; k <<= 1)
        warp_finish(sh, seg, gseg, lane, k >> 1, k);
    __syncthreads();

    // k = 256..2048: block steps j>=128, warp finish
    for (int k = 256; k <= 2048; k <<= 1) {
        for (int j = k >> 1; j >= 128; j >>= 1)
            block_step(sh, base, tid, j, k);
        warp_finish(sh, seg, gseg, lane, 64, k);
        __syncthreads();
    }

    // ---- k=4096: cross-CTA j=2048, local j<=1024 ----
    exchange(sh, shbase, rank ^ 1, ((rank ^ (rank >> 1)) & 1) == 0, tid);
    for (int j = 1024; j >= 128; j >>= 1)
        block_step(sh, base, tid, j, 4096);
    warp_finish(sh, seg, gseg, lane, 64, 4096);
    __syncthreads();

    // ---- k=8192 (asc): cross j=4096, j=2048, local j<=1024 ----
    exchange(sh, shbase, rank ^ 2, rank < 2, tid);
    exchange(sh, shbase, rank ^ 1, (rank & 1) == 0, tid);
    for (int j = 1024; j >= 128; j >>= 1)
        block_step(sh, base, tid, j, 8192);
    warp_finish(sh, seg, gseg, lane, 64, 8192);
    __syncthreads();

    // ---- extract sorted keys + inverse permutation ----
    u64* gk  = g_keys + row * NN + base;
    int* inv = g_inv  + row * NN;
    for (int l = tid; l < 2048; l += 512) {
        u64 key = sh[l];
        gk[l] = key;
        inv[(u32)key & 8191u] = base + l;
    }
}

// -------------------------------------------------------------------------
// Windows + perm generation: one warp per window.
// REMAP: block covers (b, p0..p0+1) x ALL 4 h -> the block's perm output is
// one fully contiguous 32KB span (better L2-slice/DRAM streaming).
//   warp wib: dp = wib>>2, h = wib&3; p = 2*g + dp; row = b*4 + h.
// -------------------------------------------------------------------------
__global__ void __launch_bounds__(256) windowsW(float* __restrict__ out) {
    const unsigned FULL = 0xFFFFFFFFu;
    const float E_M8  = 3.3546262790251185e-4f;   // exp(-8)
    const float E_P56 = 2.0916595960130657e+24f;  // exp(56)
    int lane = threadIdx.x & 31;
    int wib  = threadIdx.x >> 5;                  // 0..7
    int b    = blockIdx.x >> 12;                  // 0..1
    int g    = blockIdx.x & 4095;                 // p-group
    int p    = (g << 1) | (wib >> 2);
    int h    = wib & 3;
    int row  = (b << 2) | h;
    int rb   = row * NN;

    int s   = g_inv[rb + p];
    int pos = (s + lane) & (NN - 1);
    u64 key = g_keys[rb + pos];
    int idx = (int)((u32)key & 8191u);
    u32 u   = (u32)(key >> 32);

    u32 prevu = __shfl_up_sync(FULL, u, 1);
    int eq = (lane > 0 && pos != 0 && u == prevu) ? 1 : 0;
    unsigned mask = __ballot_sync(FULL, eq);

    int t = lane;
    unsigned above = (t == 31) ? 0u : (mask >> (t + 1));
    int t1 = t + (__ffs(~above) - 1);                // tie-run end
    unsigned below = ~mask & (0xFFFFFFFFu >> (31 - t));
    int t0 = 31 - __clz(below);                      // tie-run start
    int m  = NN - s; if (m > 32) m = 32;             // wrap point
    int greater = (t < m) ? (m - 1 - t1) : (m + 31 - t1);
    int rank = greater + (t - t0);

    int pack = (idx << 6) | rank;                    // idx distinct -> stable
#pragma unroll
    for (int k2 = 2; k2 <= 32; k2 <<= 1) {
#pragma unroll
        for (int j = k2 >> 1; j > 0; j >>= 1) {
            int o = __shfl_xor_sync(FULL, pack, j);
            bool asc = ((lane & k2) == 0);
            bool low = ((lane & j) == 0);
            bool take = (asc == low) ? (o < pack) : (o > pack);
            if (take) pack = o;
        }
    }

    __stcs(out + (size_t)IDX_BASE + (size_t)(rb + p) * NK + lane,
           (float)(pack >> 6));
    int rk = pack & 63;

    float e = __expf(-2.0f * (float)lane);           // lane m holds exp(-2m)
    int c0 = (lane & 7) * 4;
    int arow = lane >> 3;

    int mm[4]; float v[4];
    {
        int r0 = __shfl_sync(FULL, rk, c0);
        int r1 = __shfl_sync(FULL, rk, c0 + 1);
        int r2 = __shfl_sync(FULL, rk, c0 + 2);
        int r3 = __shfl_sync(FULL, rk, c0 + 3);
        mm[0] = (arow - r0) & 31;  mm[1] = (arow - r1) & 31;
        mm[2] = (arow - r2) & 31;  mm[3] = (arow - r3) & 31;
        v[0] = __shfl_sync(FULL, e, mm[0]);
        v[1] = __shfl_sync(FULL, e, mm[1]);
        v[2] = __shfl_sync(FULL, e, mm[2]);
        v[3] = __shfl_sync(FULL, e, mm[3]);
    }

    float* po = out + ((size_t)((b * NN + p) * NH + h) << 10);  // (B,N,H,K,K)

    __stcs(reinterpret_cast<float4*>(po + arow * 32 + c0),
           make_float4(v[0], v[1], v[2], v[3]));
#pragma unroll
    for (int rnd = 1; rnd < 8; rnd++) {
#pragma unroll
        for (int c = 0; c < 4; c++) {
            mm[c] += 4;
            bool wrap = mm[c] >= 32;
            v[c] *= wrap ? E_P56 : E_M8;
            if (wrap) mm[c] -= 32;
        }
        int a = rnd * 4 + arow;
        __stcs(reinterpret_cast<float4*>(po + a * 32 + c0),
               make_float4(v[0], v[1], v[2], v[3]));
    }
}

extern "C" void kernel_launch(void* const* d_in, const int* in_sizes, int n_in,
                              void* d_out, int out_size) {
    const float* ranking = (const float*)d_in[0];   // (B,H,N,1) f32
    float* out = (float*)d_out;

    sortCluster<<<32, 512>>>(ranking);
    windowsW<<<8192, 256>>>(out);
}